// round 9
// baseline (speedup 1.0000x reference)
#include <cuda_runtime.h>
#include <cuda_bf16.h>

#define D_DIM   1024
#define DV      256            // float4 groups per row
#define L_COMP  16384
#define L_FULL  32768
#define NCHUNK  2048
#define CL      8              // L_COMP / NCHUNK
#define EPSF    1e-4f

// Scratch (allocation-free: __device__ globals)
__device__ float  g_aggA[NCHUNK];            // per-chunk decay product
__device__ float4 g_aggB[NCHUNK * DV];       // per-chunk local-scan final value
__device__ float4 g_pref[NCHUNK * DV];       // inclusive prefix through chunk c
__device__ int    g_flag[NCHUNK];            // 0=none, 1=aggregate ready, 2=prefix ready
__device__ int    g_pos[L_COMP + 1];         // boundary positions; pos[L_COMP]=L_FULL

// ---------------------------------------------------------------------------
// k0: clear lookback flags (graph replays!) + boundary positions via
//     batched loads and ballot/popc block scan.
// ---------------------------------------------------------------------------
__global__ void k0_pos(const int* __restrict__ b) {
    __shared__ int wsum[32];
    int tid  = threadIdx.x;
    int lane = tid & 31;
    int wid  = tid >> 5;

    g_flag[tid] = 0;                         // reset decoupled-lookback flags
    g_flag[tid + 1024] = 0;
    if (tid == 0) g_pos[L_COMP] = L_FULL;

    int vals[32];
    #pragma unroll
    for (int k = 0; k < 32; k++) vals[k] = b[k * 1024 + tid];

    unsigned lemask = (2u << lane) - 1u;
    int carry = 0;
    #pragma unroll 1
    for (int k = 0; k < 32; k++) {
        unsigned m = __ballot_sync(0xFFFFFFFFu, vals[k] != 0);
        int incl = __popc(m & lemask);
        if (lane == 0) wsum[wid] = __popc(m);
        __syncthreads();
        if (wid == 0) {
            int s = wsum[lane];
            #pragma unroll
            for (int o = 1; o < 32; o <<= 1) {
                int n = __shfl_up_sync(0xFFFFFFFFu, s, o);
                if (lane >= o) s += n;
            }
            wsum[lane] = s;
        }
        __syncthreads();
        int excl = wid ? wsum[wid - 1] : 0;
        if (vals[k]) g_pos[carry + excl + incl - 1] = k * 1024 + tid;
        carry += wsum[31];
        __syncthreads();
    }
    __threadfence();                         // flags + pos visible before k_scan
}

// ---------------------------------------------------------------------------
// k_scan: single-pass scan, ONE read of x.
//   Local scan held in registers (CL=8 -> 8 float4, computed in-place over the
//   load buffer). Global fixup is z_t = z_local_t + cumA_t * Z0 with scalar
//   cumA_t, so no second pass over x. Decoupled lookback provides Z0.
// ---------------------------------------------------------------------------
__global__ __launch_bounds__(256) void k_scan(const float4* __restrict__ x,
                                              const float* __restrict__ p,
                                              float4* __restrict__ out) {
    int c   = blockIdx.x;
    int tid = threadIdx.x;
    int t0  = c * CL;

    __shared__ float s_p[CL], s_a[CL];
    __shared__ int   s_pos[CL + 1];
    __shared__ int   s_flag;

    if (tid < CL) {
        float pt = fminf(fmaxf(p[t0 + tid], EPSF), 1.0f - EPSF);
        s_p[tid] = pt;
        s_a[tid] = 1.0f - pt;
    }
    if (tid < CL + 1) s_pos[tid] = g_pos[t0 + tid];
    __syncthreads();

    const float4* xr = x + (size_t)t0 * DV + tid;

    // ---- Pass A: load chunk (8-deep MLP) + in-place local scan ----
    float4 zv[CL];
    #pragma unroll
    for (int k = 0; k < CL; k++) zv[k] = __ldcg(&xr[(size_t)k * DV]);

    float A = s_a[0];
    {
        float p0 = s_p[0];
        zv[0].x *= p0; zv[0].y *= p0; zv[0].z *= p0; zv[0].w *= p0;
    }
    #pragma unroll
    for (int k = 1; k < CL; k++) {
        float a = s_a[k], pt = s_p[k];
        zv[k].x = fmaf(a, zv[k-1].x, pt * zv[k].x);
        zv[k].y = fmaf(a, zv[k-1].y, pt * zv[k].y);
        zv[k].z = fmaf(a, zv[k-1].z, pt * zv[k].z);
        zv[k].w = fmaf(a, zv[k-1].w, pt * zv[k].w);
        A *= a;
    }
    float4 B = zv[CL - 1];

    float4 z0;   // state entering this chunk

    if (c == 0) {
        z0 = make_float4(0.f, 0.f, 0.f, 0.f);
        g_pref[tid] = B;
        __threadfence();
        __syncthreads();
        if (tid == 0) atomicExch(&g_flag[0], 2);
    } else {
        // publish aggregate
        g_aggB[c * DV + tid] = B;
        if (tid == 0) g_aggA[c] = A;
        __threadfence();
        __syncthreads();
        if (tid == 0) atomicExch(&g_flag[c], 1);

        // ---- decoupled lookback ----
        float  As = 1.0f;
        float4 Bs = make_float4(0.f, 0.f, 0.f, 0.f);
        int j = c - 1;
        while (true) {
            if (tid == 0) {
                int f;
                do {
                    f = *((volatile int*)(g_flag + j));
                    if (f == 0) __nanosleep(40);
                } while (f == 0);
                s_flag = f;
            }
            __syncthreads();
            int f = s_flag;
            if (f == 2) {
                float4 Pj = __ldcg(&g_pref[j * DV + tid]);
                z0.x = fmaf(As, Pj.x, Bs.x);
                z0.y = fmaf(As, Pj.y, Bs.y);
                z0.z = fmaf(As, Pj.z, Bs.z);
                z0.w = fmaf(As, Pj.w, Bs.w);
                break;
            }
            float  Aj = __ldcg(&g_aggA[j]);
            float4 Bj = __ldcg(&g_aggB[j * DV + tid]);
            Bs.x = fmaf(As, Bj.x, Bs.x);
            Bs.y = fmaf(As, Bj.y, Bs.y);
            Bs.z = fmaf(As, Bj.z, Bs.z);
            Bs.w = fmaf(As, Bj.w, Bs.w);
            As *= Aj;
            j--;
            if (j < 0) { z0 = Bs; break; }   // unreachable (flag[0]->2), but safe
            __syncthreads();                 // protect s_flag reuse
        }

        // publish inclusive prefix: P_c = A*Z0 + B
        float4 P;
        P.x = fmaf(A, z0.x, B.x);
        P.y = fmaf(A, z0.y, B.y);
        P.z = fmaf(A, z0.z, B.z);
        P.w = fmaf(A, z0.w, B.w);
        g_pref[c * DV + tid] = P;
        __threadfence();
        __syncthreads();
        if (tid == 0) atomicExch(&g_flag[c], 2);
    }

    // ---- fixup + fused gather emit: z_t = z_local_t + cumA_t * Z0 ----
    float cum = 1.0f;
    #pragma unroll
    for (int t = 0; t < CL; t++) {
        cum *= s_a[t];
        float4 z;
        z.x = fmaf(cum, z0.x, zv[t].x);
        z.y = fmaf(cum, z0.y, zv[t].y);
        z.z = fmaf(cum, z0.z, zv[t].z);
        z.w = fmaf(cum, z0.w, zv[t].w);
        int s = s_pos[t], e = s_pos[t + 1];
        for (int jj = s; jj < e; jj++)
            __stcs(&out[(size_t)jj * DV + tid], z);
    }
}

// ---------------------------------------------------------------------------
extern "C" void kernel_launch(void* const* d_in, const int* in_sizes, int n_in,
                              void* d_out, int out_size) {
    const float* x = (const float*)d_in[0];        // (1, 16384, 1024) fp32
    const float* p = (const float*)d_in[1];        // (16384,) fp32
    const int*   b = (const int*)d_in[2];          // (1, 32768) int32
    float* out = (float*)d_out;                    // (1, 32768, 1024) fp32

    k0_pos<<<1, 1024>>>(b);
    k_scan<<<NCHUNK, 256>>>((const float4*)x, p, (float4*)out);
}

// round 12
// speedup vs baseline: 1.2235x; 1.2235x over previous
#include <cuda_runtime.h>
#include <cuda_bf16.h>

#define D_DIM   1024
#define DV      256            // float4 groups per row
#define L_COMP  16384
#define L_FULL  32768
#define NCHUNK  1024
#define CL      16             // L_COMP / NCHUNK
#define SC      32             // chunks per superchunk
#define NSUPER  32             // NCHUNK / SC
#define GRID    512            // persistent blocks (all resident: 4/SM x 148)
#define CPB     (NCHUNK / GRID) // chunks per block = 2
#define EPSF    1e-4f

// Scratch (allocation-free: __device__ globals)
__device__ float  g_A[NCHUNK];               // per-chunk decay product
__device__ float4 g_B[NCHUNK * DV];          // per-chunk local aggregate
__device__ float4 g_Z0[NCHUNK * DV];         // state entering each chunk
__device__ float  g_As[NSUPER];              // superchunk decay product
__device__ float4 g_Bs[NSUPER * DV];         // superchunk aggregate
__device__ float4 g_Z0s[NSUPER * DV];        // state entering each superchunk
__device__ int    g_pos[L_COMP + 1];         // boundary positions; pos[L_COMP]=L_FULL
__device__ int            g_count;           // grid barrier counter
__device__ volatile int   g_sense;           // grid barrier sense

// ---------------------------------------------------------------------------
// Sense-reversal grid barrier. All GRID blocks resident (64-reg cap via
// launch_bounds -> 4 blocks/SM; 512 <= 592), so spinning cannot deadlock.
// Release fence before sense flip; acquire fence after spin exit.
// ---------------------------------------------------------------------------
__device__ __forceinline__ void grid_bar(int& sense) {
    __syncthreads();
    sense ^= 1;
    if (threadIdx.x == 0) {
        __threadfence();                              // release
        if (atomicAdd(&g_count, 1) == GRID - 1) {
            atomicExch(&g_count, 0);
            __threadfence();
            g_sense = sense;
        } else {
            while (g_sense != sense) __nanosleep(32);
            __threadfence();                          // acquire
        }
    }
    __syncthreads();
}

// ---------------------------------------------------------------------------
// k0: reset barrier state (graph replays!) + boundary positions via batched
//     loads and ballot/popc block scan.
// ---------------------------------------------------------------------------
__global__ void k0_pos(const int* __restrict__ b) {
    __shared__ int wsum[32];
    int tid  = threadIdx.x;
    int lane = tid & 31;
    int wid  = tid >> 5;

    if (tid == 0) { g_count = 0; g_sense = 0; g_pos[L_COMP] = L_FULL; }

    int vals[32];
    #pragma unroll
    for (int k = 0; k < 32; k++) vals[k] = b[k * 1024 + tid];

    unsigned lemask = (2u << lane) - 1u;
    int carry = 0;
    #pragma unroll 1
    for (int k = 0; k < 32; k++) {
        unsigned m = __ballot_sync(0xFFFFFFFFu, vals[k] != 0);
        int incl = __popc(m & lemask);
        if (lane == 0) wsum[wid] = __popc(m);
        __syncthreads();
        if (wid == 0) {
            int s = wsum[lane];
            #pragma unroll
            for (int o = 1; o < 32; o <<= 1) {
                int n = __shfl_up_sync(0xFFFFFFFFu, s, o);
                if (lane >= o) s += n;
            }
            wsum[lane] = s;
        }
        __syncthreads();
        int excl = wid ? wsum[wid - 1] : 0;
        if (vals[k]) g_pos[carry + excl + incl - 1] = k * 1024 + tid;
        carry += wsum[31];
        __syncthreads();
    }
    __threadfence();
}

// ---------------------------------------------------------------------------
// k_all: persistent kernel, all scan phases + fused-gather emit.
// ---------------------------------------------------------------------------
__global__ __launch_bounds__(256, 4) void k_all(const float4* __restrict__ x,
                                                const float* __restrict__ p,
                                                float4* __restrict__ out) {
    int bid = blockIdx.x;
    int tid = threadIdx.x;
    int sense = 0;

    __shared__ float s_p[CPB][CL], s_a[CPB][CL];

    // ---- Phase A: per-chunk aggregates (grid-stride over chunks) ----
    #pragma unroll
    for (int r = 0; r < CPB; r++) {
        int c = bid + r * GRID;
        if (c >= NCHUNK) break;
        int t0 = c * CL;
        if (tid < CL) {
            float pt = fminf(fmaxf(p[t0 + tid], EPSF), 1.0f - EPSF);
            s_p[r][tid] = pt;
            s_a[r][tid] = 1.0f - pt;
        }
        __syncthreads();

        const float4* xr = x + (size_t)t0 * DV + tid;
        float4 B = make_float4(0.f, 0.f, 0.f, 0.f);
        float  A = 1.0f;
        #pragma unroll
        for (int tb = 0; tb < CL; tb += 8) {
            float4 xv[8];
            #pragma unroll
            for (int k = 0; k < 8; k++) xv[k] = __ldcg(&xr[(size_t)(tb + k) * DV]);
            #pragma unroll
            for (int k = 0; k < 8; k++) {
                float a = s_a[r][tb + k], pt = s_p[r][tb + k];
                B.x = fmaf(a, B.x, pt * xv[k].x);
                B.y = fmaf(a, B.y, pt * xv[k].y);
                B.z = fmaf(a, B.z, pt * xv[k].z);
                B.w = fmaf(a, B.w, pt * xv[k].w);
                A *= a;
            }
        }
        g_B[(size_t)c * DV + tid] = B;
        if (tid == 0) g_A[c] = A;
    }
    grid_bar(sense);

    // ---- Phase B1: superchunk aggregates (32 blocks) ----
    if (bid < NSUPER) {
        int c0 = bid * SC;
        __shared__ float sA1[SC];
        if (tid < SC) sA1[tid] = g_A[c0 + tid];
        __syncthreads();

        float4 B = make_float4(0.f, 0.f, 0.f, 0.f);
        float  A = 1.0f;
        #pragma unroll
        for (int kb = 0; kb < SC; kb += 8) {
            float4 Bc[8];
            #pragma unroll
            for (int k = 0; k < 8; k++) Bc[k] = g_B[(size_t)(c0 + kb + k) * DV + tid];
            #pragma unroll
            for (int k = 0; k < 8; k++) {
                float a = sA1[kb + k];
                B.x = fmaf(a, B.x, Bc[k].x);
                B.y = fmaf(a, B.y, Bc[k].y);
                B.z = fmaf(a, B.z, Bc[k].z);
                B.w = fmaf(a, B.w, Bc[k].w);
                A *= a;
            }
        }
        g_Bs[(size_t)bid * DV + tid] = B;
        if (tid == 0) g_As[bid] = A;
    }
    grid_bar(sense);

    // ---- Phase B2: serial scan over 32 superchunks (1 block, L2-hot) ----
    if (bid == 0) {
        __shared__ float sA2[NSUPER];
        if (tid < NSUPER) sA2[tid] = g_As[tid];
        __syncthreads();

        float4 z = make_float4(0.f, 0.f, 0.f, 0.f);
        #pragma unroll
        for (int sb = 0; sb < NSUPER; sb += 8) {
            float4 Bs[8];
            #pragma unroll
            for (int k = 0; k < 8; k++) Bs[k] = g_Bs[(size_t)(sb + k) * DV + tid];
            #pragma unroll
            for (int k = 0; k < 8; k++) {
                g_Z0s[(size_t)(sb + k) * DV + tid] = z;
                float a = sA2[sb + k];
                z.x = fmaf(a, z.x, Bs[k].x);
                z.y = fmaf(a, z.y, Bs[k].y);
                z.z = fmaf(a, z.z, Bs[k].z);
                z.w = fmaf(a, z.w, Bs[k].w);
            }
        }
    }
    grid_bar(sense);

    // ---- Phase B3: expand superchunk prefixes -> per-chunk Z0 (32 blocks) ----
    if (bid < NSUPER) {
        int c0 = bid * SC;
        __shared__ float sA3[SC];
        if (tid < SC) sA3[tid] = g_A[c0 + tid];
        __syncthreads();

        float4 z = g_Z0s[(size_t)bid * DV + tid];
        #pragma unroll
        for (int kb = 0; kb < SC; kb += 8) {
            float4 Bc[8];
            #pragma unroll
            for (int k = 0; k < 8; k++) Bc[k] = g_B[(size_t)(c0 + kb + k) * DV + tid];
            #pragma unroll
            for (int k = 0; k < 8; k++) {
                g_Z0[(size_t)(c0 + kb + k) * DV + tid] = z;
                float a = sA3[kb + k];
                z.x = fmaf(a, z.x, Bc[k].x);
                z.y = fmaf(a, z.y, Bc[k].y);
                z.z = fmaf(a, z.z, Bc[k].z);
                z.w = fmaf(a, z.w, Bc[k].w);
            }
        }
    }
    grid_bar(sense);

    // ---- Phase C: re-scan from Z0 (x L2-hot), fused-gather emit ----
    __shared__ int s_pos[CPB][CL + 1];
    #pragma unroll
    for (int r = 0; r < CPB; r++) {
        int c = bid + r * GRID;
        if (c < NCHUNK && tid < CL + 1) s_pos[r][tid] = g_pos[c * CL + tid];
    }
    __syncthreads();

    #pragma unroll
    for (int r = 0; r < CPB; r++) {
        int c = bid + r * GRID;
        if (c >= NCHUNK) break;
        int t0 = c * CL;
        const float4* xr = x + (size_t)t0 * DV + tid;
        float4 z = g_Z0[(size_t)c * DV + tid];

        #pragma unroll
        for (int tb = 0; tb < CL; tb += 8) {
            float4 xv[8];
            #pragma unroll
            for (int k = 0; k < 8; k++) xv[k] = __ldcg(&xr[(size_t)(tb + k) * DV]);
            #pragma unroll
            for (int k = 0; k < 8; k++) {
                int t = tb + k;
                float a = s_a[r][t], pt = s_p[r][t];
                z.x = fmaf(a, z.x, pt * xv[k].x);
                z.y = fmaf(a, z.y, pt * xv[k].y);
                z.z = fmaf(a, z.z, pt * xv[k].z);
                z.w = fmaf(a, z.w, pt * xv[k].w);
                int s = s_pos[r][t], e = s_pos[r][t + 1];
                for (int jj = s; jj < e; jj++)
                    __stcs(&out[(size_t)jj * DV + tid], z);
            }
        }
    }
}

// ---------------------------------------------------------------------------
extern "C" void kernel_launch(void* const* d_in, const int* in_sizes, int n_in,
                              void* d_out, int out_size) {
    const float* x = (const float*)d_in[0];        // (1, 16384, 1024) fp32
    const float* p = (const float*)d_in[1];        // (16384,) fp32
    const int*   b = (const int*)d_in[2];          // (1, 32768) int32
    float* out = (float*)d_out;                    // (1, 32768, 1024) fp32

    k0_pos<<<1, 1024>>>(b);
    k_all<<<GRID, 256>>>((const float4*)x, p, (float4*)out);
}

// round 13
// speedup vs baseline: 1.6769x; 1.3706x over previous
#include <cuda_runtime.h>
#include <cuda_bf16.h>

#define D_DIM   1024
#define DV      256            // float4 groups per row
#define L_COMP  16384
#define L_FULL  32768
#define NCHUNK  1024
#define CL      16             // L_COMP / NCHUNK
#define SC      32             // chunks per superchunk
#define NSUPER  32             // NCHUNK / SC
#define EPSF    1e-4f

// Scratch (allocation-free: __device__ globals)
__device__ float  g_A[NCHUNK];               // per-chunk decay product
__device__ float4 g_B[NCHUNK * DV];          // per-chunk local aggregate
__device__ float4 g_Z0[NCHUNK * DV];         // state entering each chunk
__device__ float  g_As[NSUPER];              // superchunk decay product
__device__ float4 g_Bs[NSUPER * DV];         // superchunk aggregate
__device__ float4 g_Z0s[NSUPER * DV];        // state entering each superchunk
__device__ int    g_pos[L_COMP + 1];         // boundary positions; pos[L_COMP]=L_FULL
__device__ int            g_count;           // 32-block barrier counter
__device__ volatile int   g_sense;           // 32-block barrier sense

// ---------------------------------------------------------------------------
// k0: reset k2's barrier state (graph replays!) + boundary positions via
//     batched loads and ballot/popc block scan.
// ---------------------------------------------------------------------------
__global__ void k0_pos(const int* __restrict__ b) {
    __shared__ int wsum[32];
    int tid  = threadIdx.x;
    int lane = tid & 31;
    int wid  = tid >> 5;

    if (tid == 0) { g_count = 0; g_sense = 0; g_pos[L_COMP] = L_FULL; }

    int vals[32];
    #pragma unroll
    for (int k = 0; k < 32; k++) vals[k] = b[k * 1024 + tid];

    unsigned lemask = (2u << lane) - 1u;
    int carry = 0;
    #pragma unroll 1
    for (int k = 0; k < 32; k++) {
        unsigned m = __ballot_sync(0xFFFFFFFFu, vals[k] != 0);
        int incl = __popc(m & lemask);
        if (lane == 0) wsum[wid] = __popc(m);
        __syncthreads();
        if (wid == 0) {
            int s = wsum[lane];
            #pragma unroll
            for (int o = 1; o < 32; o <<= 1) {
                int n = __shfl_up_sync(0xFFFFFFFFu, s, o);
                if (lane >= o) s += n;
            }
            wsum[lane] = s;
        }
        __syncthreads();
        int excl = wid ? wsum[wid - 1] : 0;
        if (vals[k]) g_pos[carry + excl + incl - 1] = k * 1024 + tid;
        carry += wsum[31];
        __syncthreads();
    }
    __threadfence();
}

// ---------------------------------------------------------------------------
// k1: per-chunk aggregates. 1024 blocks x 256 threads, float4/thread,
//     8-deep batched loads. x allocates in L2 (re-read by k3).
// ---------------------------------------------------------------------------
__global__ __launch_bounds__(256) void k1_agg(const float4* __restrict__ x,
                                              const float* __restrict__ p) {
    int c = blockIdx.x, tid = threadIdx.x;
    int t0 = c * CL;
    __shared__ float s_p[CL], s_a[CL];
    if (tid < CL) {
        float pt = fminf(fmaxf(p[t0 + tid], EPSF), 1.0f - EPSF);
        s_p[tid] = pt;
        s_a[tid] = 1.0f - pt;
    }
    __syncthreads();

    const float4* xr = x + (size_t)t0 * DV + tid;
    float4 B = make_float4(0.f, 0.f, 0.f, 0.f);
    float  A = 1.0f;

    #pragma unroll
    for (int tb = 0; tb < CL; tb += 8) {
        float4 xv[8];
        #pragma unroll
        for (int k = 0; k < 8; k++) xv[k] = __ldcg(&xr[(size_t)(tb + k) * DV]);
        #pragma unroll
        for (int k = 0; k < 8; k++) {
            float a = s_a[tb + k], pt = s_p[tb + k];
            B.x = fmaf(a, B.x, pt * xv[k].x);
            B.y = fmaf(a, B.y, pt * xv[k].y);
            B.z = fmaf(a, B.z, pt * xv[k].z);
            B.w = fmaf(a, B.w, pt * xv[k].w);
            A *= a;
        }
    }
    g_B[(size_t)c * DV + tid] = B;
    if (tid == 0) g_A[c] = A;
}

// ---------------------------------------------------------------------------
// k2: fused chunk-prefix tree in ONE kernel. 32 blocks (all trivially
//     resident), two internal grid barriers among the 32 blocks.
//     B1: superchunk aggregates  ->  B2: block 0 scans 32 supers  ->
//     B3: expand to per-chunk Z0.
// ---------------------------------------------------------------------------
__device__ __forceinline__ void bar32(int& sense) {
    __syncthreads();
    sense ^= 1;
    if (threadIdx.x == 0) {
        __threadfence();                              // release
        if (atomicAdd(&g_count, 1) == NSUPER - 1) {
            atomicExch(&g_count, 0);
            __threadfence();
            g_sense = sense;
        } else {
            while (g_sense != sense) __nanosleep(32);
            __threadfence();                          // acquire
        }
    }
    __syncthreads();
}

__global__ __launch_bounds__(256) void k2_fused() {
    int bid = blockIdx.x;                             // 0..31
    int tid = threadIdx.x;
    int sense = 0;
    int c0 = bid * SC;

    __shared__ float sA[SC];
    if (tid < SC) sA[tid] = g_A[c0 + tid];
    __syncthreads();

    // ---- B1: superchunk aggregate ----
    {
        float4 B = make_float4(0.f, 0.f, 0.f, 0.f);
        float  A = 1.0f;
        #pragma unroll
        for (int kb = 0; kb < SC; kb += 8) {
            float4 Bc[8];
            #pragma unroll
            for (int k = 0; k < 8; k++) Bc[k] = g_B[(size_t)(c0 + kb + k) * DV + tid];
            #pragma unroll
            for (int k = 0; k < 8; k++) {
                float a = sA[kb + k];
                B.x = fmaf(a, B.x, Bc[k].x);
                B.y = fmaf(a, B.y, Bc[k].y);
                B.z = fmaf(a, B.z, Bc[k].z);
                B.w = fmaf(a, B.w, Bc[k].w);
                A *= a;
            }
        }
        g_Bs[(size_t)bid * DV + tid] = B;
        if (tid == 0) g_As[bid] = A;
    }
    bar32(sense);

    // ---- B2: block 0 scans the 32 superchunk aggregates ----
    if (bid == 0) {
        __shared__ float sAs[NSUPER];
        if (tid < NSUPER) sAs[tid] = g_As[tid];
        __syncthreads();

        float4 z = make_float4(0.f, 0.f, 0.f, 0.f);
        #pragma unroll
        for (int sb = 0; sb < NSUPER; sb += 8) {
            float4 Bs[8];
            #pragma unroll
            for (int k = 0; k < 8; k++) Bs[k] = g_Bs[(size_t)(sb + k) * DV + tid];
            #pragma unroll
            for (int k = 0; k < 8; k++) {
                g_Z0s[(size_t)(sb + k) * DV + tid] = z;
                float a = sAs[sb + k];
                z.x = fmaf(a, z.x, Bs[k].x);
                z.y = fmaf(a, z.y, Bs[k].y);
                z.z = fmaf(a, z.z, Bs[k].z);
                z.w = fmaf(a, z.w, Bs[k].w);
            }
        }
    }
    bar32(sense);

    // ---- B3: expand superchunk prefixes -> per-chunk Z0 ----
    {
        float4 z = g_Z0s[(size_t)bid * DV + tid];
        #pragma unroll
        for (int kb = 0; kb < SC; kb += 8) {
            float4 Bc[8];
            #pragma unroll
            for (int k = 0; k < 8; k++) Bc[k] = g_B[(size_t)(c0 + kb + k) * DV + tid];
            #pragma unroll
            for (int k = 0; k < 8; k++) {
                g_Z0[(size_t)(c0 + kb + k) * DV + tid] = z;
                float a = sA[kb + k];
                z.x = fmaf(a, z.x, Bc[k].x);
                z.y = fmaf(a, z.y, Bc[k].y);
                z.z = fmaf(a, z.z, Bc[k].z);
                z.w = fmaf(a, z.w, Bc[k].w);
            }
        }
    }
}

// ---------------------------------------------------------------------------
// k3: re-scan each chunk from Z0 (x re-read L2-hot), scatter z_t directly
//     into contiguous out rows [pos[t], pos[t+1]) with streaming stores.
// ---------------------------------------------------------------------------
__global__ __launch_bounds__(256) void k3_emit(const float4* __restrict__ x,
                                               const float* __restrict__ p,
                                               float4* __restrict__ out) {
    int c = blockIdx.x, tid = threadIdx.x;
    int t0 = c * CL;
    __shared__ float s_p[CL], s_a[CL];
    __shared__ int   s_pos[CL + 1];
    if (tid < CL) {
        float pt = fminf(fmaxf(p[t0 + tid], EPSF), 1.0f - EPSF);
        s_p[tid] = pt;
        s_a[tid] = 1.0f - pt;
    }
    if (tid < CL + 1) s_pos[tid] = g_pos[t0 + tid];
    __syncthreads();

    const float4* xr = x + (size_t)t0 * DV + tid;
    float4 z = g_Z0[(size_t)c * DV + tid];

    #pragma unroll
    for (int tb = 0; tb < CL; tb += 8) {
        float4 xv[8];
        #pragma unroll
        for (int k = 0; k < 8; k++) xv[k] = __ldcg(&xr[(size_t)(tb + k) * DV]);
        #pragma unroll
        for (int k = 0; k < 8; k++) {
            int t = tb + k;
            float a = s_a[t], pt = s_p[t];
            z.x = fmaf(a, z.x, pt * xv[k].x);
            z.y = fmaf(a, z.y, pt * xv[k].y);
            z.z = fmaf(a, z.z, pt * xv[k].z);
            z.w = fmaf(a, z.w, pt * xv[k].w);
            int s = s_pos[t], e = s_pos[t + 1];
            for (int jj = s; jj < e; jj++)
                __stcs(&out[(size_t)jj * DV + tid], z);
        }
    }
}

// ---------------------------------------------------------------------------
extern "C" void kernel_launch(void* const* d_in, const int* in_sizes, int n_in,
                              void* d_out, int out_size) {
    const float* x = (const float*)d_in[0];        // (1, 16384, 1024) fp32
    const float* p = (const float*)d_in[1];        // (16384,) fp32
    const int*   b = (const int*)d_in[2];          // (1, 32768) int32
    float* out = (float*)d_out;                    // (1, 32768, 1024) fp32

    k0_pos<<<1, 1024>>>(b);
    k1_agg<<<NCHUNK, 256>>>((const float4*)x, p);
    k2_fused<<<NSUPER, 256>>>();
    k3_emit<<<NCHUNK, 256>>>((const float4*)x, p, (float4*)out);
}

// round 15
// speedup vs baseline: 1.6975x; 1.0122x over previous
#include <cuda_runtime.h>
#include <cuda_bf16.h>

#define D_DIM   1024
#define DV      256            // float4 groups per row
#define L_COMP  16384
#define L_FULL  32768
#define NCHUNK  512
#define CL      32             // L_COMP / NCHUNK
#define SC      32             // chunks per superchunk
#define NSUPER  16             // NCHUNK / SC
#define NSLICE  8              // channel slices for the tree kernels
#define SLICEW  32             // float4 channels per slice (DV / NSLICE)
#define EPSF    1e-4f

// Scratch (allocation-free: __device__ globals)
__device__ float  g_A[NCHUNK];               // per-chunk decay product
__device__ float4 g_B[NCHUNK * DV];          // per-chunk local aggregate
__device__ float4 g_Z0[NCHUNK * DV];         // state entering each chunk
__device__ float  g_As[NSUPER];              // superchunk decay product
__device__ float4 g_Bs[NSUPER * DV];         // superchunk aggregate
__device__ float4 g_Z0s[NSUPER * DV];        // state entering each superchunk
__device__ int    g_pos[L_COMP + 1];         // boundary positions; pos[L_COMP]=L_FULL

// ---------------------------------------------------------------------------
// k0: boundary positions via batched loads and ballot/popc block scan.
// ---------------------------------------------------------------------------
__global__ void k0_pos(const int* __restrict__ b) {
    __shared__ int wsum[32];
    int tid  = threadIdx.x;
    int lane = tid & 31;
    int wid  = tid >> 5;

    if (tid == 0) g_pos[L_COMP] = L_FULL;

    int vals[32];
    #pragma unroll
    for (int k = 0; k < 32; k++) vals[k] = b[k * 1024 + tid];

    unsigned lemask = (2u << lane) - 1u;
    int carry = 0;
    #pragma unroll 1
    for (int k = 0; k < 32; k++) {
        unsigned m = __ballot_sync(0xFFFFFFFFu, vals[k] != 0);
        int incl = __popc(m & lemask);
        if (lane == 0) wsum[wid] = __popc(m);
        __syncthreads();
        if (wid == 0) {
            int s = wsum[lane];
            #pragma unroll
            for (int o = 1; o < 32; o <<= 1) {
                int n = __shfl_up_sync(0xFFFFFFFFu, s, o);
                if (lane >= o) s += n;
            }
            wsum[lane] = s;
        }
        __syncthreads();
        int excl = wid ? wsum[wid - 1] : 0;
        if (vals[k]) g_pos[carry + excl + incl - 1] = k * 1024 + tid;
        carry += wsum[31];
        __syncthreads();
    }
    __threadfence();
}

// ---------------------------------------------------------------------------
// k1: per-chunk aggregates. 512 blocks x 256 threads, float4/thread,
//     8-deep batched loads. x allocates in L2 (re-read by k3).
// ---------------------------------------------------------------------------
__global__ __launch_bounds__(256) void k1_agg(const float4* __restrict__ x,
                                              const float* __restrict__ p) {
    int c = blockIdx.x, tid = threadIdx.x;
    int t0 = c * CL;
    __shared__ float s_p[CL], s_a[CL];
    if (tid < CL) {
        float pt = fminf(fmaxf(p[t0 + tid], EPSF), 1.0f - EPSF);
        s_p[tid] = pt;
        s_a[tid] = 1.0f - pt;
    }
    __syncthreads();

    const float4* xr = x + (size_t)t0 * DV + tid;
    float4 B = make_float4(0.f, 0.f, 0.f, 0.f);
    float  A = 1.0f;

    #pragma unroll
    for (int tb = 0; tb < CL; tb += 8) {
        float4 xv[8];
        #pragma unroll
        for (int k = 0; k < 8; k++) xv[k] = __ldcg(&xr[(size_t)(tb + k) * DV]);
        #pragma unroll
        for (int k = 0; k < 8; k++) {
            float a = s_a[tb + k], pt = s_p[tb + k];
            B.x = fmaf(a, B.x, pt * xv[k].x);
            B.y = fmaf(a, B.y, pt * xv[k].y);
            B.z = fmaf(a, B.z, pt * xv[k].z);
            B.w = fmaf(a, B.w, pt * xv[k].w);
            A *= a;
        }
    }
    g_B[(size_t)c * DV + tid] = B;
    if (tid == 0) g_A[c] = A;
}

// ---------------------------------------------------------------------------
// kB1: superchunk aggregates, channel-sliced. 128 blocks (16 supers x 8
//      slices). 8 warp-subgroups each combine 4 chunk aggregates; smem fold
//      across subgroups (A values are scalars, so the fold is cheap).
// ---------------------------------------------------------------------------
__global__ __launch_bounds__(256) void kB1_super() {
    int s    = blockIdx.x / NSLICE;
    int j    = blockIdx.x % NSLICE;
    int tid  = threadIdx.x;
    int g    = tid >> 5;                     // subgroup 0..7
    int lane = tid & 31;
    int v    = j * SLICEW + lane;            // float4 channel index
    int c0   = s * SC;

    __shared__ float  sA[SC];
    __shared__ float4 sB[NSLICE][SLICEW];
    __shared__ float  sAg[NSLICE];
    if (tid < SC) sA[tid] = g_A[c0 + tid];
    __syncthreads();

    // subgroup g combines chunks c0+4g .. c0+4g+3 (in order)
    float4 Bg = make_float4(0.f, 0.f, 0.f, 0.f);
    float  Ag = 1.0f;
    #pragma unroll
    for (int i = 0; i < 4; i++) {
        int cc = 4 * g + i;
        float4 bb = g_B[(size_t)(c0 + cc) * DV + v];
        float  a  = sA[cc];
        Bg.x = fmaf(a, Bg.x, bb.x);
        Bg.y = fmaf(a, Bg.y, bb.y);
        Bg.z = fmaf(a, Bg.z, bb.z);
        Bg.w = fmaf(a, Bg.w, bb.w);
        Ag *= a;
    }
    sB[g][lane] = Bg;
    if (lane == 0) sAg[g] = Ag;
    __syncthreads();

    if (g == 0) {                            // 32 threads fold 8 subgroups
        float4 B = make_float4(0.f, 0.f, 0.f, 0.f);
        float  A = 1.0f;
        #pragma unroll
        for (int gg = 0; gg < NSLICE; gg++) {
            float a = sAg[gg];
            float4 bb = sB[gg][lane];
            B.x = fmaf(a, B.x, bb.x);
            B.y = fmaf(a, B.y, bb.y);
            B.z = fmaf(a, B.z, bb.z);
            B.w = fmaf(a, B.w, bb.w);
            A *= a;
        }
        g_Bs[(size_t)s * DV + v] = B;
        if (lane == 0 && j == 0) g_As[s] = A;
    }
}

// ---------------------------------------------------------------------------
// kB2: serial scan over the 16 superchunk aggregates. 1 block, 256 threads,
//      everything prefetched (64 KB, L2-hot). ~2 us.
// ---------------------------------------------------------------------------
__global__ __launch_bounds__(256) void kB2_scan() {
    int v = threadIdx.x;
    __shared__ float sAs[NSUPER];
    if (v < NSUPER) sAs[v] = g_As[v];
    __syncthreads();

    float4 z = make_float4(0.f, 0.f, 0.f, 0.f);
    #pragma unroll
    for (int sb = 0; sb < NSUPER; sb += 8) {
        float4 Bs[8];
        #pragma unroll
        for (int k = 0; k < 8; k++) Bs[k] = g_Bs[(size_t)(sb + k) * DV + v];
        #pragma unroll
        for (int k = 0; k < 8; k++) {
            g_Z0s[(size_t)(sb + k) * DV + v] = z;
            float a = sAs[sb + k];
            z.x = fmaf(a, z.x, Bs[k].x);
            z.y = fmaf(a, z.y, Bs[k].y);
            z.z = fmaf(a, z.z, Bs[k].z);
            z.w = fmaf(a, z.w, Bs[k].w);
        }
    }
}

// ---------------------------------------------------------------------------
// kB3: expand superchunk prefixes -> per-chunk Z0, channel-sliced.
//      128 blocks; subgroup-parallel within superchunk.
// ---------------------------------------------------------------------------
__global__ __launch_bounds__(256) void kB3_expand() {
    int s    = blockIdx.x / NSLICE;
    int j    = blockIdx.x % NSLICE;
    int tid  = threadIdx.x;
    int g    = tid >> 5;
    int lane = tid & 31;
    int v    = j * SLICEW + lane;
    int c0   = s * SC;

    __shared__ float  sA[SC];
    __shared__ float4 sB[NSLICE][SLICEW];
    __shared__ float  sAg[NSLICE];
    if (tid < SC) sA[tid] = g_A[c0 + tid];
    __syncthreads();

    // load the 4 chunk aggregates this subgroup owns (reused for expand)
    float4 bb[4];
    #pragma unroll
    for (int i = 0; i < 4; i++)
        bb[i] = g_B[(size_t)(c0 + 4 * g + i) * DV + v];

    // subgroup aggregate
    float4 Bg = make_float4(0.f, 0.f, 0.f, 0.f);
    float  Ag = 1.0f;
    #pragma unroll
    for (int i = 0; i < 4; i++) {
        float a = sA[4 * g + i];
        Bg.x = fmaf(a, Bg.x, bb[i].x);
        Bg.y = fmaf(a, Bg.y, bb[i].y);
        Bg.z = fmaf(a, Bg.z, bb[i].z);
        Bg.w = fmaf(a, Bg.w, bb[i].w);
        Ag *= a;
    }
    sB[g][lane] = Bg;
    if (lane == 0) sAg[g] = Ag;
    __syncthreads();

    // state entering this subgroup: fold preceding subgroups onto Z0s
    float4 z = g_Z0s[(size_t)s * DV + v];
    for (int gg = 0; gg < g; gg++) {
        float a = sAg[gg];
        float4 bs = sB[gg][lane];
        z.x = fmaf(a, z.x, bs.x);
        z.y = fmaf(a, z.y, bs.y);
        z.z = fmaf(a, z.z, bs.z);
        z.w = fmaf(a, z.w, bs.w);
    }

    // expand: write Z0 for each chunk, then advance
    #pragma unroll
    for (int i = 0; i < 4; i++) {
        int cc = c0 + 4 * g + i;
        g_Z0[(size_t)cc * DV + v] = z;
        float a = sA[4 * g + i];
        z.x = fmaf(a, z.x, bb[i].x);
        z.y = fmaf(a, z.y, bb[i].y);
        z.z = fmaf(a, z.z, bb[i].z);
        z.w = fmaf(a, z.w, bb[i].w);
    }
}

// ---------------------------------------------------------------------------
// k3: re-scan each chunk from Z0 (x re-read L2-hot), scatter z_t directly
//     into contiguous out rows [pos[t], pos[t+1]) with streaming stores.
// ---------------------------------------------------------------------------
__global__ __launch_bounds__(256) void k3_emit(const float4* __restrict__ x,
                                               const float* __restrict__ p,
                                               float4* __restrict__ out) {
    int c = blockIdx.x, tid = threadIdx.x;
    int t0 = c * CL;
    __shared__ float s_p[CL], s_a[CL];
    __shared__ int   s_pos[CL + 1];
    if (tid < CL) {
        float pt = fminf(fmaxf(p[t0 + tid], EPSF), 1.0f - EPSF);
        s_p[tid] = pt;
        s_a[tid] = 1.0f - pt;
    }
    if (tid < CL + 1) s_pos[tid] = g_pos[t0 + tid];
    __syncthreads();

    const float4* xr = x + (size_t)t0 * DV + tid;
    float4 z = g_Z0[(size_t)c * DV + tid];

    #pragma unroll
    for (int tb = 0; tb < CL; tb += 8) {
        float4 xv[8];
        #pragma unroll
        for (int k = 0; k < 8; k++) xv[k] = __ldcg(&xr[(size_t)(tb + k) * DV]);
        #pragma unroll
        for (int k = 0; k < 8; k++) {
            int t = tb + k;
            float a = s_a[t], pt = s_p[t];
            z.x = fmaf(a, z.x, pt * xv[k].x);
            z.y = fmaf(a, z.y, pt * xv[k].y);
            z.z = fmaf(a, z.z, pt * xv[k].z);
            z.w = fmaf(a, z.w, pt * xv[k].w);
            int s = s_pos[t], e = s_pos[t + 1];
            for (int jj = s; jj < e; jj++)
                __stcs(&out[(size_t)jj * DV + tid], z);
        }
    }
}

// ---------------------------------------------------------------------------
extern "C" void kernel_launch(void* const* d_in, const int* in_sizes, int n_in,
                              void* d_out, int out_size) {
    const float* x = (const float*)d_in[0];        // (1, 16384, 1024) fp32
    const float* p = (const float*)d_in[1];        // (16384,) fp32
    const int*   b = (const int*)d_in[2];          // (1, 32768) int32
    float* out = (float*)d_out;                    // (1, 32768, 1024) fp32

    k0_pos<<<1, 1024>>>(b);
    k1_agg<<<NCHUNK, 256>>>((const float4*)x, p);
    kB1_super<<<NSUPER * NSLICE, 256>>>();
    kB2_scan<<<1, 256>>>();
    kB3_expand<<<NSUPER * NSLICE, 256>>>();
    k3_emit<<<NCHUNK, 256>>>((const float4*)x, p, (float4*)out);
}